// round 14
// baseline (speedup 1.0000x reference)
#include <cuda_runtime.h>
#include <cuda_bf16.h>
#include <cuda_fp16.h>
#include <cstdint>
#include <cstddef>

#define B_ROWS 4096
#define DDIM   512
#define KN     16384
#define NGRP   (KN / 8)      // 2048 8-col groups per row
#define NDT    (DDIM / 32)   // 16 d-tiles in transw
#define EPSV   1e-6f
#define DELTA  4.0f

// ---------------- device scratch (no allocation allowed) ----------------
__device__ __nv_bfloat16 gXb[(size_t)B_ROWS * DDIM];   // X bf16 row-major (b,d)
__device__ __nv_bfloat16 gWt[(size_t)KN * DDIM];       // W^T bf16 row-major (n,d)
__device__ float         gWt32[(size_t)KN * DDIM];     // W^T fp32 (n,d) for refine
__device__ __half        gGmin[(size_t)B_ROWS * NGRP]; // per-(row, 8col-group) d2 min
__device__ float         g_cp1[NDT * KN];              // col partial sums (per d-tile)
__device__ float         g_cp2[NDT * KN];              // col partial sumsq
__device__ float         g_c[KN];                      // exact col stats
__device__ float         g_r[B_ROWS];                  // exact row stats
__device__ float         g_dist[B_ROWS];               // per-row exact min dist

// ---------------- helpers ----------------
__device__ __forceinline__ uint32_t smem_u32(const void* p) {
    uint32_t a;
    asm("{ .reg .u64 t; cvta.to.shared.u64 t, %1; cvt.u32.u64 %0, t; }" : "=r"(a) : "l"(p));
    return a;
}
__device__ __forceinline__ void cpa16(uint32_t dst, const void* src) {
    asm volatile("cp.async.cg.shared.global [%0], [%1], 16;\n" :: "r"(dst), "l"(src));
}
#define CP_COMMIT() asm volatile("cp.async.commit_group;\n" ::: "memory")
#define CP_WAIT(n)  asm volatile("cp.async.wait_group %0;\n" :: "n"(n) : "memory")

__device__ __forceinline__ void ldsm_x4(uint32_t addr, uint32_t r[4]) {
    asm volatile("ldmatrix.sync.aligned.m8n8.x4.shared.b16 {%0,%1,%2,%3}, [%4];"
        : "=r"(r[0]), "=r"(r[1]), "=r"(r[2]), "=r"(r[3]) : "r"(addr));
}
__device__ __forceinline__ void mma_bf16(float c[4], const uint32_t a[4],
                                         uint32_t b0, uint32_t b1) {
    asm volatile("mma.sync.aligned.m16n8k16.row.col.f32.bf16.bf16.f32 "
        "{%0,%1,%2,%3}, {%4,%5,%6,%7}, {%8,%9}, {%0,%1,%2,%3};"
        : "+f"(c[0]), "+f"(c[1]), "+f"(c[2]), "+f"(c[3])
        : "r"(a[0]), "r"(a[1]), "r"(a[2]), "r"(a[3]), "r"(b0), "r"(b1));
}

// ---------------- fused prep: blocks [0,8192) = W transpose+col partials,
// blocks [8192,10240) = X conv + row stats (2 rows per block) ----------------
__global__ void prep_kernel(const float* __restrict__ X, const float* __restrict__ W) {
    if (blockIdx.x < 8192) {
        const int bx = blockIdx.x & 511;
        const int by = blockIdx.x >> 9;
        const int tx = threadIdx.x & 31;
        const int ty = threadIdx.x >> 5;   // 0..7
        __shared__ float t[32][33];
        __shared__ float ps[8][32], ps2[8][32];
        int x = bx * 32 + tx;  // n
        int y = by * 32 + ty;  // d
        #pragma unroll
        for (int j = 0; j < 32; j += 8)
            t[ty + j][tx] = W[(size_t)(y + j) * KN + x];
        __syncthreads();
        int nx = by * 32 + tx;  // d
        int ny = bx * 32 + ty;  // n
        #pragma unroll
        for (int j = 0; j < 32; j += 8) {
            float v = t[tx][ty + j];
            gWt32[(size_t)(ny + j) * DDIM + nx] = v;
            gWt[(size_t)(ny + j) * DDIM + nx] = __float2bfloat16(v);
        }
        float s = 0.f, s2 = 0.f;
        #pragma unroll
        for (int j = 0; j < 4; ++j) {
            float w = t[ty + j * 8][tx];
            s += w;
            s2 = fmaf(w, w, s2);
        }
        ps[ty][tx] = s;
        ps2[ty][tx] = s2;
        __syncthreads();
        if (ty == 0) {
            float S = 0.f, S2 = 0.f;
            #pragma unroll
            for (int j = 0; j < 8; ++j) { S += ps[j][tx]; S2 += ps2[j][tx]; }
            g_cp1[by * KN + bx * 32 + tx] = S;
            g_cp2[by * KN + bx * 32 + tx] = S2;
        }
    } else {
        const int b = (blockIdx.x - 8192) * 2 + (threadIdx.x >> 7);
        const int t = threadIdx.x & 127;
        float4 v = ((const float4*)(X + (size_t)b * DDIM))[t];
        __nv_bfloat162* xb = (__nv_bfloat162*)(gXb + (size_t)b * DDIM);
        xb[2 * t]     = __floats2bfloat162_rn(v.x, v.y);
        xb[2 * t + 1] = __floats2bfloat162_rn(v.z, v.w);
        float s = v.x + v.y + v.z + v.w;
        float s2 = v.x * v.x + v.y * v.y + v.z * v.z + v.w * v.w;
        #pragma unroll
        for (int o = 16; o; o >>= 1) {
            s  += __shfl_xor_sync(0xFFFFFFFFu, s,  o);
            s2 += __shfl_xor_sync(0xFFFFFFFFu, s2, o);
        }
        __shared__ float sh[2][8];
        int sub = threadIdx.x >> 7;
        int w = (t >> 5);
        if ((t & 31) == 0) { sh[sub][w] = s; sh[sub][4 + w] = s2; }
        __syncthreads();
        if (t == 0) {
            float S = sh[sub][0] + sh[sub][1] + sh[sub][2] + sh[sub][3];
            float S2 = sh[sub][4] + sh[sub][5] + sh[sub][6] + sh[sub][7];
            g_r[b] = S2 + 2.f * EPSV * S + (float)DDIM * EPSV * EPSV;
        }
    }
}

__global__ void col_finalize_kernel() {
    int k = blockIdx.x * blockDim.x + threadIdx.x;
    if (k >= KN) return;
    float s = 0.f, s2 = 0.f;
    #pragma unroll
    for (int j = 0; j < NDT; ++j) { s += g_cp1[j * KN + k]; s2 += g_cp2[j * KN + k]; }
    g_c[k] = s2 - 2.f * EPSV * s;
}

// ---- bf16 mma.sync GEMM, 128x128 tile, Kc=64, 3-stage cp.async pipeline ----
#define SM_COL   0
#define SM_ROW   512
#define SM_A0    2048
#define SM_A1    18432
#define SM_A2    34816
#define SM_B0    51200
#define SM_B1    67584
#define SM_B2    83968
#define SMEM_TOT 100352

__global__ void __launch_bounds__(256, 2)
gemm_kernel() {
    extern __shared__ char smem[];
    const uint32_t sb = smem_u32(smem);
    const int tid  = threadIdx.x;
    const int wid  = tid >> 5;
    const int lane = tid & 31;
    const int wm = wid >> 2;
    const int wn = wid & 3;
    const int rowBase = blockIdx.y * 128;
    const int colBase = blockIdx.x * 128;

    float* sCol = (float*)(smem + SM_COL);
    float* sRow = (float*)(smem + SM_ROW);

    if (tid < 128) {
        sCol[tid] = g_c[colBase + tid];
        sRow[tid] = g_r[rowBase + tid];
    }

    const uint32_t offA[3] = {SM_A0, SM_A1, SM_A2};
    const uint32_t offB[3] = {SM_B0, SM_B1, SM_B2};

    auto load_chunk = [&](int c, int stg) {
        const char* As = (const char*)(gXb + (size_t)rowBase * DDIM) + c * 128;
        const char* Bs = (const char*)(gWt + (size_t)colBase * DDIM) + c * 128;
        #pragma unroll
        for (int i = 0; i < 4; ++i) {
            int g = tid + i * 256;
            int r = g >> 3, gi = g & 7;
            uint32_t d = r * 128 + ((gi * 16) ^ ((r & 7) << 4));
            cpa16(sb + offA[stg] + d, As + (size_t)r * 1024 + gi * 16);
        }
        #pragma unroll
        for (int i = 0; i < 4; ++i) {
            int g = tid + i * 256;
            int n = g >> 3, gi = g & 7;
            uint32_t d = n * 128 + ((gi * 16) ^ ((n & 7) << 4));
            cpa16(sb + offB[stg] + d, Bs + (size_t)n * 1024 + gi * 16);
        }
        CP_COMMIT();
    };

    uint32_t baseA[4], patA[4];
    #pragma unroll
    for (int mi = 0; mi < 4; ++mi) {
        int r = wm * 64 + mi * 16 + (lane & 15);
        baseA[mi] = r * 128;
        patA[mi]  = (r & 7) << 4;
    }
    const uint32_t aQuad = (lane >> 4) * 16;
    uint32_t baseB[2], patB[2];
    #pragma unroll
    for (int bi = 0; bi < 2; ++bi) {
        int n = wn * 32 + bi * 16 + (lane & 7) + ((lane >> 4) << 3);
        baseB[bi] = n * 128;
        patB[bi]  = (n & 7) << 4;
    }
    const uint32_t bQuad = ((lane >> 3) & 1) * 16;

    float acc[4][4][4];
    #pragma unroll
    for (int a = 0; a < 4; ++a)
        #pragma unroll
        for (int b = 0; b < 4; ++b)
            #pragma unroll
            for (int q = 0; q < 4; ++q) acc[a][b][q] = 0.f;

    load_chunk(0, 0);
    load_chunk(1, 1);

    #pragma unroll
    for (int c = 0; c < 8; ++c) {
        if (c == 7) { CP_WAIT(0); } else { CP_WAIT(1); }
        __syncthreads();
        if (c + 2 < 8) load_chunk(c + 2, (c + 2) % 3);

        const uint32_t aBuf = sb + offA[c % 3];
        const uint32_t bBuf = sb + offB[c % 3];
        #pragma unroll
        for (int kk = 0; kk < 4; ++kk) {
            const uint32_t kb = kk * 32;
            uint32_t af[4][4], bf[2][4];
            #pragma unroll
            for (int mi = 0; mi < 4; ++mi)
                ldsm_x4(aBuf + baseA[mi] + ((kb + aQuad) ^ patA[mi]), af[mi]);
            #pragma unroll
            for (int bi = 0; bi < 2; ++bi)
                ldsm_x4(bBuf + baseB[bi] + ((kb + bQuad) ^ patB[bi]), bf[bi]);
            #pragma unroll
            for (int mi = 0; mi < 4; ++mi)
                #pragma unroll
                for (int bi = 0; bi < 2; ++bi) {
                    mma_bf16(acc[mi][bi * 2 + 0], af[mi], bf[bi][0], bf[bi][1]);
                    mma_bf16(acc[mi][bi * 2 + 1], af[mi], bf[bi][2], bf[bi][3]);
                }
        }
    }

    // ---- epilogue: per-(row, 8col-group) d2 mins -> gGmin ----
    const int tig = lane & 3;
    const int g   = lane >> 2;
    float gm0[4][4], gm1[4][4];
    #pragma unroll
    for (int mi = 0; mi < 4; ++mi) {
        const int r0 = wm * 64 + mi * 16 + g;
        const int r1 = r0 + 8;
        const float rr0 = sRow[r0], rr1 = sRow[r1];
        #pragma unroll
        for (int j = 0; j < 4; ++j) {
            const int cb = wn * 32 + j * 8 + 2 * tig;
            const float cc0 = sCol[cb], cc1 = sCol[cb + 1];
            float m0 = fminf(rr0 + cc0 - 2.f * acc[mi][j][0],
                             rr0 + cc1 - 2.f * acc[mi][j][1]);
            float m1 = fminf(rr1 + cc0 - 2.f * acc[mi][j][2],
                             rr1 + cc1 - 2.f * acc[mi][j][3]);
            m0 = fminf(m0, __shfl_xor_sync(0xFFFFFFFFu, m0, 1));
            m0 = fminf(m0, __shfl_xor_sync(0xFFFFFFFFu, m0, 2));
            m1 = fminf(m1, __shfl_xor_sync(0xFFFFFFFFu, m1, 1));
            m1 = fminf(m1, __shfl_xor_sync(0xFFFFFFFFu, m1, 2));
            gm0[mi][j] = m0;
            gm1[mi][j] = m1;
        }
    }
    if (tig == 0) {
        const int gcol = blockIdx.x * 16 + wn * 4;
        #pragma unroll
        for (int mi = 0; mi < 4; ++mi) {
            const int r0 = rowBase + wm * 64 + mi * 16 + g;
            const int r1 = r0 + 8;
            __half2 a0 = __floats2half2_rn(gm0[mi][0], gm0[mi][1]);
            __half2 a1 = __floats2half2_rn(gm0[mi][2], gm0[mi][3]);
            __half2 b0 = __floats2half2_rn(gm1[mi][0], gm1[mi][1]);
            __half2 b1 = __floats2half2_rn(gm1[mi][2], gm1[mi][3]);
            uint2 v0, v1;
            v0.x = *(uint32_t*)&a0; v0.y = *(uint32_t*)&a1;
            v1.x = *(uint32_t*)&b0; v1.y = *(uint32_t*)&b1;
            *(uint2*)(gGmin + (size_t)r0 * NGRP + gcol) = v0;
            *(uint2*)(gGmin + (size_t)r1 * NGRP + gcol) = v1;
        }
    }
}

// ------- refine: warp-per-row, full 256-uint4 row coverage -------
__global__ void __launch_bounds__(256)
refine_kernel(const float* __restrict__ X,
              const float* __restrict__ loc,
              float* __restrict__ out, int out_size) {
    const int wrp = threadIdx.x >> 5;
    const int lane = threadIdx.x & 31;
    const int b = blockIdx.x * 8 + wrp;

    __shared__ uint4 sg[8][256];     // staged group-min rows (4KB each row)
    __shared__ int scnt[8];
    __shared__ int scand[8][64];

    if (lane == 0) scnt[wrp] = 0;

    // pass 1: load FULL row (256 uint4 = 2048 groups), stage, track min
    const uint4* gp = (const uint4*)(gGmin + (size_t)b * NGRP);
    float m = 3.0e38f;
    #pragma unroll
    for (int i = 0; i < 8; ++i) {
        uint4 v = gp[i * 32 + lane];
        sg[wrp][i * 32 + lane] = v;
        const uint32_t ww[4] = {v.x, v.y, v.z, v.w};
        #pragma unroll
        for (int q = 0; q < 4; ++q) {
            __half2 p = *(const __half2*)&ww[q];
            m = fminf(m, fminf(__low2float(p), __high2float(p)));
        }
    }
    #pragma unroll
    for (int o = 16; o; o >>= 1) m = fminf(m, __shfl_xor_sync(0xFFFFFFFFu, m, o));
    const float thr = m + DELTA;
    __syncwarp();

    // pass 2: candidate groups from smem
    #pragma unroll
    for (int i = 0; i < 8; ++i) {
        uint4 v = sg[wrp][i * 32 + lane];
        const uint32_t ww[4] = {v.x, v.y, v.z, v.w};
        #pragma unroll
        for (int q = 0; q < 4; ++q) {
            __half2 p = *(const __half2*)&ww[q];
            int gbase = (i * 32 + lane) * 8 + 2 * q;
            if (__low2float(p) <= thr) {
                int pp = atomicAdd(&scnt[wrp], 1);
                if (pp < 64) scand[wrp][pp] = gbase;
            }
            if (__high2float(p) <= thr) {
                int pp = atomicAdd(&scnt[wrp], 1);
                if (pp < 64) scand[wrp][pp] = gbase + 1;
            }
        }
    }
    __syncwarp();
    const int ng = min(scnt[wrp], 64);

    const float4* xr = (const float4*)(X + (size_t)b * DDIM);
    float4 xv[4];
    #pragma unroll
    for (int i = 0; i < 4; ++i) xv[i] = xr[i * 32 + lane];
    const float rb = g_r[b];

    unsigned long long best = 0xFFFFFFFFFFFFFFFFULL;
    for (int ci = 0; ci < ng * 8; ++ci) {
        const int k = scand[wrp][ci >> 3] * 8 + (ci & 7);
        const float4* wr = (const float4*)(gWt32 + (size_t)k * DDIM);
        float s = 0.f;
        #pragma unroll
        for (int i = 0; i < 4; ++i) {
            float4 w = wr[i * 32 + lane];
            s = fmaf(xv[i].x, w.x, s);
            s = fmaf(xv[i].y, w.y, s);
            s = fmaf(xv[i].z, w.z, s);
            s = fmaf(xv[i].w, w.w, s);
        }
        #pragma unroll
        for (int o = 16; o; o >>= 1) s += __shfl_xor_sync(0xFFFFFFFFu, s, o);
        if (lane == 0) {
            float d2 = rb + g_c[k] - 2.f * s;
            unsigned u = __float_as_uint(d2);
            u = (u & 0x80000000u) ? ~u : (u | 0x80000000u);
            unsigned long long key = ((unsigned long long)u << 32) | (unsigned)k;
            if (key < best) best = key;
        }
    }

    if (lane == 0) {
        unsigned k = (unsigned)(best & 0xFFFFFFFFu);
        unsigned u = (unsigned)(best >> 32);
        u = (u & 0x80000000u) ? (u & 0x7FFFFFFFu) : ~u;
        float d2 = __uint_as_float(u);
        g_dist[b] = sqrtf(fmaxf(d2, 0.f));
        out[2 * b] = loc[2 * k];
        if (2 * b + 1 < out_size - 1) out[2 * b + 1] = loc[2 * k + 1];
    }
}

__global__ void loss_kernel(float* __restrict__ out, int out_size) {
    __shared__ float sh[1024];
    float local = 0.f;
    for (int b = threadIdx.x; b < B_ROWS; b += 1024) local += g_dist[b];
    sh[threadIdx.x] = local;
    __syncthreads();
    #pragma unroll
    for (int s = 512; s > 0; s >>= 1) {
        if (threadIdx.x < s) sh[threadIdx.x] += sh[threadIdx.x + s];
        __syncthreads();
    }
    if (threadIdx.x == 0) out[out_size - 1] = sh[0] / (float)B_ROWS;
}

// ---------------------------------------------------------------------------
extern "C" void kernel_launch(void* const* d_in, const int* in_sizes, int n_in,
                              void* d_out, int out_size) {
    const float* X = (const float*)d_in[0];  // (4096, 512)
    const float* W = (const float*)d_in[1];  // (512, 16384)
    const float* L = (const float*)d_in[2];  // (16384, 2)
    float* out = (float*)d_out;

    cudaFuncSetAttribute(gemm_kernel, cudaFuncAttributeMaxDynamicSharedMemorySize, SMEM_TOT);

    prep_kernel<<<8192 + B_ROWS / 2, 256>>>(X, W);
    col_finalize_kernel<<<KN / 256, 256>>>();

    gemm_kernel<<<dim3(KN / 128, B_ROWS / 128), 256, SMEM_TOT>>>();

    refine_kernel<<<B_ROWS / 8, 256>>>(X, L, out, out_size);
    loss_kernel<<<1, 1024>>>(out, out_size);
}

// round 15
// speedup vs baseline: 1.1032x; 1.1032x over previous
#include <cuda_runtime.h>
#include <cuda_bf16.h>
#include <cuda_fp16.h>
#include <cstdint>
#include <cstddef>

#define B_ROWS 4096
#define DDIM   512
#define KN     16384
#define NGRP   (KN / 8)      // 2048 8-col groups per row
#define NDT    (DDIM / 32)   // 16 d-tiles in transw
#define EPSV   1e-6f
#define DELTA  4.0f

// ---------------- device scratch (no allocation allowed) ----------------
__device__ __nv_bfloat16 gXb[(size_t)B_ROWS * DDIM];   // X bf16 row-major (b,d)
__device__ __nv_bfloat16 gWt[(size_t)KN * DDIM];       // W^T bf16 row-major (n,d)
__device__ float         gWt32[(size_t)KN * DDIM];     // W^T fp32 (n,d) for refine
__device__ __half        gGmin[(size_t)B_ROWS * NGRP]; // per-(row, 8col-group) d2 min
__device__ float         g_cp1[NDT * KN];              // col partial sums (per d-tile)
__device__ float         g_cp2[NDT * KN];              // col partial sumsq
__device__ float         g_c[KN];                      // exact col stats
__device__ float         g_r[B_ROWS];                  // exact row stats
__device__ unsigned      g_amin[B_ROWS];               // approx per-row min (f32 bits)
__device__ float         g_dist[B_ROWS];               // per-row exact min dist

// ---------------- helpers ----------------
__device__ __forceinline__ uint32_t smem_u32(const void* p) {
    uint32_t a;
    asm("{ .reg .u64 t; cvta.to.shared.u64 t, %1; cvt.u32.u64 %0, t; }" : "=r"(a) : "l"(p));
    return a;
}
__device__ __forceinline__ void cpa16(uint32_t dst, const void* src) {
    asm volatile("cp.async.cg.shared.global [%0], [%1], 16;\n" :: "r"(dst), "l"(src));
}
#define CP_COMMIT() asm volatile("cp.async.commit_group;\n" ::: "memory")
#define CP_WAIT(n)  asm volatile("cp.async.wait_group %0;\n" :: "n"(n) : "memory")

__device__ __forceinline__ void ldsm_x4(uint32_t addr, uint32_t r[4]) {
    asm volatile("ldmatrix.sync.aligned.m8n8.x4.shared.b16 {%0,%1,%2,%3}, [%4];"
        : "=r"(r[0]), "=r"(r[1]), "=r"(r[2]), "=r"(r[3]) : "r"(addr));
}
__device__ __forceinline__ void mma_bf16(float c[4], const uint32_t a[4],
                                         uint32_t b0, uint32_t b1) {
    asm volatile("mma.sync.aligned.m16n8k16.row.col.f32.bf16.bf16.f32 "
        "{%0,%1,%2,%3}, {%4,%5,%6,%7}, {%8,%9}, {%0,%1,%2,%3};"
        : "+f"(c[0]), "+f"(c[1]), "+f"(c[2]), "+f"(c[3])
        : "r"(a[0]), "r"(a[1]), "r"(a[2]), "r"(a[3]), "r"(b0), "r"(b1));
}

// ---------------- fused prep: blocks [0,8192) = W transpose+col partials,
// blocks [8192,10240) = X conv + row stats (2 rows per block) ----------------
__global__ void prep_kernel(const float* __restrict__ X, const float* __restrict__ W) {
    if (blockIdx.x < 8192) {
        const int bx = blockIdx.x & 511;
        const int by = blockIdx.x >> 9;
        const int tx = threadIdx.x & 31;
        const int ty = threadIdx.x >> 5;   // 0..7
        __shared__ float t[32][33];
        __shared__ float ps[8][32], ps2[8][32];
        int x = bx * 32 + tx;  // n
        int y = by * 32 + ty;  // d
        #pragma unroll
        for (int j = 0; j < 32; j += 8)
            t[ty + j][tx] = W[(size_t)(y + j) * KN + x];
        __syncthreads();
        int nx = by * 32 + tx;  // d
        int ny = bx * 32 + ty;  // n
        #pragma unroll
        for (int j = 0; j < 32; j += 8) {
            float v = t[tx][ty + j];
            gWt32[(size_t)(ny + j) * DDIM + nx] = v;
            gWt[(size_t)(ny + j) * DDIM + nx] = __float2bfloat16(v);
        }
        float s = 0.f, s2 = 0.f;
        #pragma unroll
        for (int j = 0; j < 4; ++j) {
            float w = t[ty + j * 8][tx];
            s += w;
            s2 = fmaf(w, w, s2);
        }
        ps[ty][tx] = s;
        ps2[ty][tx] = s2;
        __syncthreads();
        if (ty == 0) {
            float S = 0.f, S2 = 0.f;
            #pragma unroll
            for (int j = 0; j < 8; ++j) { S += ps[j][tx]; S2 += ps2[j][tx]; }
            g_cp1[by * KN + bx * 32 + tx] = S;
            g_cp2[by * KN + bx * 32 + tx] = S2;
        }
    } else {
        const int b = (blockIdx.x - 8192) * 2 + (threadIdx.x >> 7);
        const int t = threadIdx.x & 127;
        float4 v = ((const float4*)(X + (size_t)b * DDIM))[t];
        __nv_bfloat162* xb = (__nv_bfloat162*)(gXb + (size_t)b * DDIM);
        xb[2 * t]     = __floats2bfloat162_rn(v.x, v.y);
        xb[2 * t + 1] = __floats2bfloat162_rn(v.z, v.w);
        float s = v.x + v.y + v.z + v.w;
        float s2 = v.x * v.x + v.y * v.y + v.z * v.z + v.w * v.w;
        #pragma unroll
        for (int o = 16; o; o >>= 1) {
            s  += __shfl_xor_sync(0xFFFFFFFFu, s,  o);
            s2 += __shfl_xor_sync(0xFFFFFFFFu, s2, o);
        }
        __shared__ float sh[2][8];
        int sub = threadIdx.x >> 7;
        int w = (t >> 5);
        if ((t & 31) == 0) { sh[sub][w] = s; sh[sub][4 + w] = s2; }
        __syncthreads();
        if (t == 0) {
            float S = sh[sub][0] + sh[sub][1] + sh[sub][2] + sh[sub][3];
            float S2 = sh[sub][4] + sh[sub][5] + sh[sub][6] + sh[sub][7];
            g_r[b] = S2 + 2.f * EPSV * S + (float)DDIM * EPSV * EPSV;
        }
    }
}

// also initializes g_amin for the GEMM's atomicMin (runs before gemm in-stream)
__global__ void col_finalize_kernel() {
    int k = blockIdx.x * blockDim.x + threadIdx.x;
    if (k < B_ROWS) g_amin[k] = 0x7F800000u;  // +inf
    if (k >= KN) return;
    float s = 0.f, s2 = 0.f;
    #pragma unroll
    for (int j = 0; j < NDT; ++j) { s += g_cp1[j * KN + k]; s2 += g_cp2[j * KN + k]; }
    g_c[k] = s2 - 2.f * EPSV * s;
}

// ---- bf16 mma.sync GEMM, 128x128 tile, Kc=64, 3-stage cp.async pipeline ----
#define SM_COL   0
#define SM_ROW   512
#define SM_A0    2048
#define SM_A1    18432
#define SM_A2    34816
#define SM_B0    51200
#define SM_B1    67584
#define SM_B2    83968
#define SMEM_TOT 100352

__global__ void __launch_bounds__(256, 2)
gemm_kernel() {
    extern __shared__ char smem[];
    const uint32_t sb = smem_u32(smem);
    const int tid  = threadIdx.x;
    const int wid  = tid >> 5;
    const int lane = tid & 31;
    const int wm = wid >> 2;
    const int wn = wid & 3;
    const int rowBase = blockIdx.y * 128;
    const int colBase = blockIdx.x * 128;

    float* sCol = (float*)(smem + SM_COL);
    float* sRow = (float*)(smem + SM_ROW);

    if (tid < 128) {
        sCol[tid] = g_c[colBase + tid];
        sRow[tid] = g_r[rowBase + tid];
    }

    const uint32_t offA[3] = {SM_A0, SM_A1, SM_A2};
    const uint32_t offB[3] = {SM_B0, SM_B1, SM_B2};

    auto load_chunk = [&](int c, int stg) {
        const char* As = (const char*)(gXb + (size_t)rowBase * DDIM) + c * 128;
        const char* Bs = (const char*)(gWt + (size_t)colBase * DDIM) + c * 128;
        #pragma unroll
        for (int i = 0; i < 4; ++i) {
            int g = tid + i * 256;
            int r = g >> 3, gi = g & 7;
            uint32_t d = r * 128 + ((gi * 16) ^ ((r & 7) << 4));
            cpa16(sb + offA[stg] + d, As + (size_t)r * 1024 + gi * 16);
        }
        #pragma unroll
        for (int i = 0; i < 4; ++i) {
            int g = tid + i * 256;
            int n = g >> 3, gi = g & 7;
            uint32_t d = n * 128 + ((gi * 16) ^ ((n & 7) << 4));
            cpa16(sb + offB[stg] + d, Bs + (size_t)n * 1024 + gi * 16);
        }
        CP_COMMIT();
    };

    uint32_t baseA[4], patA[4];
    #pragma unroll
    for (int mi = 0; mi < 4; ++mi) {
        int r = wm * 64 + mi * 16 + (lane & 15);
        baseA[mi] = r * 128;
        patA[mi]  = (r & 7) << 4;
    }
    const uint32_t aQuad = (lane >> 4) * 16;
    uint32_t baseB[2], patB[2];
    #pragma unroll
    for (int bi = 0; bi < 2; ++bi) {
        int n = wn * 32 + bi * 16 + (lane & 7) + ((lane >> 4) << 3);
        baseB[bi] = n * 128;
        patB[bi]  = (n & 7) << 4;
    }
    const uint32_t bQuad = ((lane >> 3) & 1) * 16;

    float acc[4][4][4];
    #pragma unroll
    for (int a = 0; a < 4; ++a)
        #pragma unroll
        for (int b = 0; b < 4; ++b)
            #pragma unroll
            for (int q = 0; q < 4; ++q) acc[a][b][q] = 0.f;

    load_chunk(0, 0);
    load_chunk(1, 1);

    #pragma unroll
    for (int c = 0; c < 8; ++c) {
        if (c == 7) { CP_WAIT(0); } else { CP_WAIT(1); }
        __syncthreads();
        if (c + 2 < 8) load_chunk(c + 2, (c + 2) % 3);

        const uint32_t aBuf = sb + offA[c % 3];
        const uint32_t bBuf = sb + offB[c % 3];
        #pragma unroll
        for (int kk = 0; kk < 4; ++kk) {
            const uint32_t kb = kk * 32;
            uint32_t af[4][4], bf[2][4];
            #pragma unroll
            for (int mi = 0; mi < 4; ++mi)
                ldsm_x4(aBuf + baseA[mi] + ((kb + aQuad) ^ patA[mi]), af[mi]);
            #pragma unroll
            for (int bi = 0; bi < 2; ++bi)
                ldsm_x4(bBuf + baseB[bi] + ((kb + bQuad) ^ patB[bi]), bf[bi]);
            #pragma unroll
            for (int mi = 0; mi < 4; ++mi)
                #pragma unroll
                for (int bi = 0; bi < 2; ++bi) {
                    mma_bf16(acc[mi][bi * 2 + 0], af[mi], bf[bi][0], bf[bi][1]);
                    mma_bf16(acc[mi][bi * 2 + 1], af[mi], bf[bi][2], bf[bi][3]);
                }
        }
    }

    // ---- epilogue: per-(row, 8col-group) d2 mins -> gGmin, row-min -> g_amin ----
    const int tig = lane & 3;
    const int g   = lane >> 2;
    float gm0[4][4], gm1[4][4];
    #pragma unroll
    for (int mi = 0; mi < 4; ++mi) {
        const int r0 = wm * 64 + mi * 16 + g;
        const int r1 = r0 + 8;
        const float rr0 = sRow[r0], rr1 = sRow[r1];
        #pragma unroll
        for (int j = 0; j < 4; ++j) {
            const int cb = wn * 32 + j * 8 + 2 * tig;
            const float cc0 = sCol[cb], cc1 = sCol[cb + 1];
            float m0 = fminf(rr0 + cc0 - 2.f * acc[mi][j][0],
                             rr0 + cc1 - 2.f * acc[mi][j][1]);
            float m1 = fminf(rr1 + cc0 - 2.f * acc[mi][j][2],
                             rr1 + cc1 - 2.f * acc[mi][j][3]);
            m0 = fminf(m0, __shfl_xor_sync(0xFFFFFFFFu, m0, 1));
            m0 = fminf(m0, __shfl_xor_sync(0xFFFFFFFFu, m0, 2));
            m1 = fminf(m1, __shfl_xor_sync(0xFFFFFFFFu, m1, 1));
            m1 = fminf(m1, __shfl_xor_sync(0xFFFFFFFFu, m1, 2));
            gm0[mi][j] = m0;
            gm1[mi][j] = m1;
        }
    }
    if (tig == 0) {
        const int gcol = blockIdx.x * 16 + wn * 4;
        #pragma unroll
        for (int mi = 0; mi < 4; ++mi) {
            const int r0 = rowBase + wm * 64 + mi * 16 + g;
            const int r1 = r0 + 8;
            __half2 a0 = __floats2half2_rn(gm0[mi][0], gm0[mi][1]);
            __half2 a1 = __floats2half2_rn(gm0[mi][2], gm0[mi][3]);
            __half2 b0 = __floats2half2_rn(gm1[mi][0], gm1[mi][1]);
            __half2 b1 = __floats2half2_rn(gm1[mi][2], gm1[mi][3]);
            uint2 v0, v1;
            v0.x = *(uint32_t*)&a0; v0.y = *(uint32_t*)&a1;
            v1.x = *(uint32_t*)&b0; v1.y = *(uint32_t*)&b1;
            *(uint2*)(gGmin + (size_t)r0 * NGRP + gcol) = v0;
            *(uint2*)(gGmin + (size_t)r1 * NGRP + gcol) = v1;
            // per-row approx min (positive floats: bit order = value order)
            float q0 = fminf(fminf(gm0[mi][0], gm0[mi][1]), fminf(gm0[mi][2], gm0[mi][3]));
            float q1 = fminf(fminf(gm1[mi][0], gm1[mi][1]), fminf(gm1[mi][2], gm1[mi][3]));
            atomicMin(&g_amin[r0], __float_as_uint(q0));
            atomicMin(&g_amin[r1], __float_as_uint(q1));
        }
    }
}

// ------- refine: single-pass scan (thr from g_amin) + exact fp32 dots -------
__global__ void refine_kernel(const float* __restrict__ X,
                              const float* __restrict__ loc,
                              float* __restrict__ out, int out_size) {
    const int b = blockIdx.x;
    const int tid = threadIdx.x;
    const int wid = tid >> 5;
    const int lane = tid & 31;
    __shared__ int cnt;
    __shared__ int grp[256];
    __shared__ unsigned long long wbest[8];
    if (tid == 0) cnt = 0;
    __syncthreads();

    const float thr = __uint_as_float(g_amin[b]) + DELTA;

    // one scan: 256 uint4 = full 2048-group row, one uint4 per thread
    const uint4 v = ((const uint4*)(gGmin + (size_t)b * NGRP))[tid];
    const uint32_t ww[4] = {v.x, v.y, v.z, v.w};
    #pragma unroll
    for (int q = 0; q < 4; ++q) {
        __half2 p = *(const __half2*)&ww[q];
        if (__low2float(p) <= thr)  { int pp = atomicAdd(&cnt, 1); if (pp < 256) grp[pp] = tid * 8 + 2 * q; }
        if (__high2float(p) <= thr) { int pp = atomicAdd(&cnt, 1); if (pp < 256) grp[pp] = tid * 8 + 2 * q + 1; }
    }
    __syncthreads();
    const int ng = min(cnt, 256);
    const int ncand = ng * 8;

    const float4* xr = (const float4*)(X + (size_t)b * DDIM);
    float4 xv[4];
    #pragma unroll
    for (int i = 0; i < 4; ++i) xv[i] = xr[i * 32 + lane];
    const float rb = g_r[b];

    unsigned long long best = 0xFFFFFFFFFFFFFFFFULL;
    for (int ci = wid; ci < ncand; ci += 8) {
        const int k = grp[ci >> 3] * 8 + (ci & 7);
        const float4* wr = (const float4*)(gWt32 + (size_t)k * DDIM);
        float s = 0.f;
        #pragma unroll
        for (int i = 0; i < 4; ++i) {
            float4 w = wr[i * 32 + lane];
            s = fmaf(xv[i].x, w.x, s);
            s = fmaf(xv[i].y, w.y, s);
            s = fmaf(xv[i].z, w.z, s);
            s = fmaf(xv[i].w, w.w, s);
        }
        #pragma unroll
        for (int o = 16; o; o >>= 1) s += __shfl_xor_sync(0xFFFFFFFFu, s, o);
        if (lane == 0) {
            float d2 = rb + g_c[k] - 2.f * s;
            unsigned u = __float_as_uint(d2);
            u = (u & 0x80000000u) ? ~u : (u | 0x80000000u);
            unsigned long long key = ((unsigned long long)u << 32) | (unsigned)k;
            if (key < best) best = key;
        }
    }
    if (lane == 0) wbest[wid] = best;
    __syncthreads();

    if (tid == 0) {
        unsigned long long bb = 0xFFFFFFFFFFFFFFFFULL;
        #pragma unroll
        for (int w = 0; w < 8; ++w) if (wbest[w] < bb) bb = wbest[w];
        unsigned k = (unsigned)(bb & 0xFFFFFFFFu);
        unsigned u = (unsigned)(bb >> 32);
        u = (u & 0x80000000u) ? (u & 0x7FFFFFFFu) : ~u;
        float d2 = __uint_as_float(u);
        g_dist[b] = sqrtf(fmaxf(d2, 0.f));
        out[2 * b] = loc[2 * k];
        if (2 * b + 1 < out_size - 1) out[2 * b + 1] = loc[2 * k + 1];
    }
}

__global__ void loss_kernel(float* __restrict__ out, int out_size) {
    __shared__ float sh[1024];
    float local = 0.f;
    for (int b = threadIdx.x; b < B_ROWS; b += 1024) local += g_dist[b];
    sh[threadIdx.x] = local;
    __syncthreads();
    #pragma unroll
    for (int s = 512; s > 0; s >>= 1) {
        if (threadIdx.x < s) sh[threadIdx.x] += sh[threadIdx.x + s];
        __syncthreads();
    }
    if (threadIdx.x == 0) out[out_size - 1] = sh[0] / (float)B_ROWS;
}

// ---------------------------------------------------------------------------
extern "C" void kernel_launch(void* const* d_in, const int* in_sizes, int n_in,
                              void* d_out, int out_size) {
    const float* X = (const float*)d_in[0];  // (4096, 512)
    const float* W = (const float*)d_in[1];  // (512, 16384)
    const float* L = (const float*)d_in[2];  // (16384, 2)
    float* out = (float*)d_out;

    cudaFuncSetAttribute(gemm_kernel, cudaFuncAttributeMaxDynamicSharedMemorySize, SMEM_TOT);

    prep_kernel<<<8192 + B_ROWS / 2, 256>>>(X, W);
    col_finalize_kernel<<<KN / 256, 256>>>();

    gemm_kernel<<<dim3(KN / 128, B_ROWS / 128), 256, SMEM_TOT>>>();

    refine_kernel<<<B_ROWS, 256>>>(X, L, out, out_size);
    loss_kernel<<<1, 1024>>>(out, out_size);
}

// round 16
// speedup vs baseline: 1.1055x; 1.0021x over previous
#include <cuda_runtime.h>
#include <cuda_bf16.h>
#include <cuda_fp16.h>
#include <cstdint>
#include <cstddef>

#define B_ROWS 4096
#define DDIM   512
#define KN     16384
#define NGRP   (KN / 8)      // 2048 8-col groups per row
#define NDT    (DDIM / 32)   // 16 d-tiles in transw
#define EPSV   1e-6f
#define DELTA  4.0f

// ---------------- device scratch (no allocation allowed) ----------------
__device__ __nv_bfloat16 gXb[(size_t)B_ROWS * DDIM];   // X bf16 row-major (b,d)
__device__ __nv_bfloat16 gWt[(size_t)KN * DDIM];       // W^T bf16 row-major (n,d)
__device__ float         gWt32[(size_t)KN * DDIM];     // W^T fp32 (n,d) for refine
__device__ __half        gGmin[(size_t)B_ROWS * NGRP]; // per-(row, 8col-group) d2 min
__device__ float         g_cp1[NDT * KN];              // col partial sums (per d-tile)
__device__ float         g_cp2[NDT * KN];              // col partial sumsq
__device__ float         g_c[KN];                      // exact col stats
__device__ float         g_r[B_ROWS];                  // exact row stats
__device__ unsigned      g_amin[B_ROWS];               // approx per-row min (f32 bits)
__device__ float         g_dist[B_ROWS];               // per-row exact min dist

// ---------------- helpers ----------------
__device__ __forceinline__ uint32_t smem_u32(const void* p) {
    uint32_t a;
    asm("{ .reg .u64 t; cvta.to.shared.u64 t, %1; cvt.u32.u64 %0, t; }" : "=r"(a) : "l"(p));
    return a;
}
__device__ __forceinline__ void cpa16(uint32_t dst, const void* src) {
    asm volatile("cp.async.cg.shared.global [%0], [%1], 16;\n" :: "r"(dst), "l"(src));
}
#define CP_COMMIT() asm volatile("cp.async.commit_group;\n" ::: "memory")
#define CP_WAIT(n)  asm volatile("cp.async.wait_group %0;\n" :: "n"(n) : "memory")

__device__ __forceinline__ void ldsm_x4(uint32_t addr, uint32_t r[4]) {
    asm volatile("ldmatrix.sync.aligned.m8n8.x4.shared.b16 {%0,%1,%2,%3}, [%4];"
        : "=r"(r[0]), "=r"(r[1]), "=r"(r[2]), "=r"(r[3]) : "r"(addr));
}
__device__ __forceinline__ void mma_bf16(float c[4], const uint32_t a[4],
                                         uint32_t b0, uint32_t b1) {
    asm volatile("mma.sync.aligned.m16n8k16.row.col.f32.bf16.bf16.f32 "
        "{%0,%1,%2,%3}, {%4,%5,%6,%7}, {%8,%9}, {%0,%1,%2,%3};"
        : "+f"(c[0]), "+f"(c[1]), "+f"(c[2]), "+f"(c[3])
        : "r"(a[0]), "r"(a[1]), "r"(a[2]), "r"(a[3]), "r"(b0), "r"(b1));
}

// ---------------- fused prep: blocks [0,8192) = W transpose+col partials,
// blocks [8192,10240) = X conv + row stats (2 rows per block) ----------------
__global__ void prep_kernel(const float* __restrict__ X, const float* __restrict__ W) {
    if (blockIdx.x < 8192) {
        const int bx = blockIdx.x & 511;
        const int by = blockIdx.x >> 9;
        const int tx = threadIdx.x & 31;
        const int ty = threadIdx.x >> 5;   // 0..7
        __shared__ float t[32][33];
        __shared__ float ps[8][32], ps2[8][32];
        int x = bx * 32 + tx;  // n
        int y = by * 32 + ty;  // d
        #pragma unroll
        for (int j = 0; j < 32; j += 8)
            t[ty + j][tx] = W[(size_t)(y + j) * KN + x];
        __syncthreads();
        int nx = by * 32 + tx;  // d
        int ny = bx * 32 + ty;  // n
        #pragma unroll
        for (int j = 0; j < 32; j += 8) {
            float v = t[tx][ty + j];
            gWt32[(size_t)(ny + j) * DDIM + nx] = v;
            gWt[(size_t)(ny + j) * DDIM + nx] = __float2bfloat16(v);
        }
        float s = 0.f, s2 = 0.f;
        #pragma unroll
        for (int j = 0; j < 4; ++j) {
            float w = t[ty + j * 8][tx];
            s += w;
            s2 = fmaf(w, w, s2);
        }
        ps[ty][tx] = s;
        ps2[ty][tx] = s2;
        __syncthreads();
        if (ty == 0) {
            float S = 0.f, S2 = 0.f;
            #pragma unroll
            for (int j = 0; j < 8; ++j) { S += ps[j][tx]; S2 += ps2[j][tx]; }
            g_cp1[by * KN + bx * 32 + tx] = S;
            g_cp2[by * KN + bx * 32 + tx] = S2;
        }
    } else {
        const int b = (blockIdx.x - 8192) * 2 + (threadIdx.x >> 7);
        const int t = threadIdx.x & 127;
        float4 v = ((const float4*)(X + (size_t)b * DDIM))[t];
        __nv_bfloat162* xb = (__nv_bfloat162*)(gXb + (size_t)b * DDIM);
        xb[2 * t]     = __floats2bfloat162_rn(v.x, v.y);
        xb[2 * t + 1] = __floats2bfloat162_rn(v.z, v.w);
        float s = v.x + v.y + v.z + v.w;
        float s2 = v.x * v.x + v.y * v.y + v.z * v.z + v.w * v.w;
        #pragma unroll
        for (int o = 16; o; o >>= 1) {
            s  += __shfl_xor_sync(0xFFFFFFFFu, s,  o);
            s2 += __shfl_xor_sync(0xFFFFFFFFu, s2, o);
        }
        __shared__ float sh[2][8];
        int sub = threadIdx.x >> 7;
        int w = (t >> 5);
        if ((t & 31) == 0) { sh[sub][w] = s; sh[sub][4 + w] = s2; }
        __syncthreads();
        if (t == 0) {
            float S = sh[sub][0] + sh[sub][1] + sh[sub][2] + sh[sub][3];
            float S2 = sh[sub][4] + sh[sub][5] + sh[sub][6] + sh[sub][7];
            g_r[b] = S2 + 2.f * EPSV * S + (float)DDIM * EPSV * EPSV;
        }
    }
}

// also initializes g_amin for the GEMM's atomicMin (runs before gemm in-stream)
__global__ void col_finalize_kernel() {
    int k = blockIdx.x * blockDim.x + threadIdx.x;
    if (k < B_ROWS) g_amin[k] = 0x7F800000u;  // +inf
    if (k >= KN) return;
    float s = 0.f, s2 = 0.f;
    #pragma unroll
    for (int j = 0; j < NDT; ++j) { s += g_cp1[j * KN + k]; s2 += g_cp2[j * KN + k]; }
    g_c[k] = s2 - 2.f * EPSV * s;
}

// ---- bf16 mma.sync GEMM, 128x128 tile, Kc=64, 3-stage cp.async pipeline ----
#define SM_COL   0
#define SM_ROW   512
#define SM_A0    2048
#define SM_A1    18432
#define SM_A2    34816
#define SM_B0    51200
#define SM_B1    67584
#define SM_B2    83968
#define SMEM_TOT 100352

__global__ void __launch_bounds__(256, 2)
gemm_kernel() {
    extern __shared__ char smem[];
    const uint32_t sb = smem_u32(smem);
    const int tid  = threadIdx.x;
    const int wid  = tid >> 5;
    const int lane = tid & 31;
    const int wm = wid >> 2;
    const int wn = wid & 3;
    const int rowBase = blockIdx.y * 128;
    const int colBase = blockIdx.x * 128;

    float* sCol = (float*)(smem + SM_COL);
    float* sRow = (float*)(smem + SM_ROW);

    if (tid < 128) {
        sCol[tid] = g_c[colBase + tid];
        sRow[tid] = g_r[rowBase + tid];
    }

    const uint32_t offA[3] = {SM_A0, SM_A1, SM_A2};
    const uint32_t offB[3] = {SM_B0, SM_B1, SM_B2};

    auto load_chunk = [&](int c, int stg) {
        const char* As = (const char*)(gXb + (size_t)rowBase * DDIM) + c * 128;
        const char* Bs = (const char*)(gWt + (size_t)colBase * DDIM) + c * 128;
        #pragma unroll
        for (int i = 0; i < 4; ++i) {
            int g = tid + i * 256;
            int r = g >> 3, gi = g & 7;
            uint32_t d = r * 128 + ((gi * 16) ^ ((r & 7) << 4));
            cpa16(sb + offA[stg] + d, As + (size_t)r * 1024 + gi * 16);
        }
        #pragma unroll
        for (int i = 0; i < 4; ++i) {
            int g = tid + i * 256;
            int n = g >> 3, gi = g & 7;
            uint32_t d = n * 128 + ((gi * 16) ^ ((n & 7) << 4));
            cpa16(sb + offB[stg] + d, Bs + (size_t)n * 1024 + gi * 16);
        }
        CP_COMMIT();
    };

    uint32_t baseA[4], patA[4];
    #pragma unroll
    for (int mi = 0; mi < 4; ++mi) {
        int r = wm * 64 + mi * 16 + (lane & 15);
        baseA[mi] = r * 128;
        patA[mi]  = (r & 7) << 4;
    }
    const uint32_t aQuad = (lane >> 4) * 16;
    uint32_t baseB[2], patB[2];
    #pragma unroll
    for (int bi = 0; bi < 2; ++bi) {
        int n = wn * 32 + bi * 16 + (lane & 7) + ((lane >> 4) << 3);
        baseB[bi] = n * 128;
        patB[bi]  = (n & 7) << 4;
    }
    const uint32_t bQuad = ((lane >> 3) & 1) * 16;

    float acc[4][4][4];
    #pragma unroll
    for (int a = 0; a < 4; ++a)
        #pragma unroll
        for (int b = 0; b < 4; ++b)
            #pragma unroll
            for (int q = 0; q < 4; ++q) acc[a][b][q] = 0.f;

    load_chunk(0, 0);
    load_chunk(1, 1);

    #pragma unroll
    for (int c = 0; c < 8; ++c) {
        if (c == 7) { CP_WAIT(0); } else { CP_WAIT(1); }
        __syncthreads();
        if (c + 2 < 8) load_chunk(c + 2, (c + 2) % 3);

        const uint32_t aBuf = sb + offA[c % 3];
        const uint32_t bBuf = sb + offB[c % 3];
        #pragma unroll
        for (int kk = 0; kk < 4; ++kk) {
            const uint32_t kb = kk * 32;
            uint32_t af[4][4], bf[2][4];
            #pragma unroll
            for (int mi = 0; mi < 4; ++mi)
                ldsm_x4(aBuf + baseA[mi] + ((kb + aQuad) ^ patA[mi]), af[mi]);
            #pragma unroll
            for (int bi = 0; bi < 2; ++bi)
                ldsm_x4(bBuf + baseB[bi] + ((kb + bQuad) ^ patB[bi]), bf[bi]);
            #pragma unroll
            for (int mi = 0; mi < 4; ++mi)
                #pragma unroll
                for (int bi = 0; bi < 2; ++bi) {
                    mma_bf16(acc[mi][bi * 2 + 0], af[mi], bf[bi][0], bf[bi][1]);
                    mma_bf16(acc[mi][bi * 2 + 1], af[mi], bf[bi][2], bf[bi][3]);
                }
        }
    }

    // ---- epilogue: per-(row, 8col-group) d2 mins -> gGmin, row-min -> g_amin ----
    const int tig = lane & 3;
    const int g   = lane >> 2;
    float gm0[4][4], gm1[4][4];
    #pragma unroll
    for (int mi = 0; mi < 4; ++mi) {
        const int r0 = wm * 64 + mi * 16 + g;
        const int r1 = r0 + 8;
        const float rr0 = sRow[r0], rr1 = sRow[r1];
        #pragma unroll
        for (int j = 0; j < 4; ++j) {
            const int cb = wn * 32 + j * 8 + 2 * tig;
            const float cc0 = sCol[cb], cc1 = sCol[cb + 1];
            float m0 = fminf(rr0 + cc0 - 2.f * acc[mi][j][0],
                             rr0 + cc1 - 2.f * acc[mi][j][1]);
            float m1 = fminf(rr1 + cc0 - 2.f * acc[mi][j][2],
                             rr1 + cc1 - 2.f * acc[mi][j][3]);
            m0 = fminf(m0, __shfl_xor_sync(0xFFFFFFFFu, m0, 1));
            m0 = fminf(m0, __shfl_xor_sync(0xFFFFFFFFu, m0, 2));
            m1 = fminf(m1, __shfl_xor_sync(0xFFFFFFFFu, m1, 1));
            m1 = fminf(m1, __shfl_xor_sync(0xFFFFFFFFu, m1, 2));
            gm0[mi][j] = m0;
            gm1[mi][j] = m1;
        }
    }
    if (tig == 0) {
        const int gcol = blockIdx.x * 16 + wn * 4;
        #pragma unroll
        for (int mi = 0; mi < 4; ++mi) {
            const int r0 = rowBase + wm * 64 + mi * 16 + g;
            const int r1 = r0 + 8;
            __half2 a0 = __floats2half2_rn(gm0[mi][0], gm0[mi][1]);
            __half2 a1 = __floats2half2_rn(gm0[mi][2], gm0[mi][3]);
            __half2 b0 = __floats2half2_rn(gm1[mi][0], gm1[mi][1]);
            __half2 b1 = __floats2half2_rn(gm1[mi][2], gm1[mi][3]);
            uint2 v0, v1;
            v0.x = *(uint32_t*)&a0; v0.y = *(uint32_t*)&a1;
            v1.x = *(uint32_t*)&b0; v1.y = *(uint32_t*)&b1;
            *(uint2*)(gGmin + (size_t)r0 * NGRP + gcol) = v0;
            *(uint2*)(gGmin + (size_t)r1 * NGRP + gcol) = v1;
            float q0 = fminf(fminf(gm0[mi][0], gm0[mi][1]), fminf(gm0[mi][2], gm0[mi][3]));
            float q1 = fminf(fminf(gm1[mi][0], gm1[mi][1]), fminf(gm1[mi][2], gm1[mi][3]));
            atomicMin(&g_amin[r0], __float_as_uint(q0));
            atomicMin(&g_amin[r1], __float_as_uint(q1));
        }
    }
}

// ------- refine: 4 rows per block, pooled candidates, exact fp32 dots -------
__global__ void __launch_bounds__(256)
refine_kernel(const float* __restrict__ X,
              const float* __restrict__ loc,
              float* __restrict__ out, int out_size) {
    const int b0 = blockIdx.x * 4;
    const int tid = threadIdx.x;
    const int wid = tid >> 5;
    const int lane = tid & 31;

    __shared__ float sx[4][DDIM];              // staged X rows (8KB)
    __shared__ int cnt;
    __shared__ int grp[512];                   // packed (row<<11 | group)
    __shared__ unsigned long long wbest[8][4];
    __shared__ float sthr[4];

    if (tid == 0) cnt = 0;
    if (tid < 4) sthr[tid] = __uint_as_float(g_amin[b0 + tid]) + DELTA;

    // stage 4 X rows: 512 float4 total, 2 per thread
    #pragma unroll
    for (int j = 0; j < 2; ++j) {
        int i = tid + j * 256;          // 0..511
        int r = i >> 7, fi = i & 127;
        ((float4*)sx[r])[fi] = ((const float4*)(X + (size_t)(b0 + r) * DDIM))[fi];
    }
    __syncthreads();

    // scan 4 group-min rows (each thread: one uint4 per row, 4 loads in flight)
    #pragma unroll
    for (int r = 0; r < 4; ++r) {
        const uint4 v = ((const uint4*)(gGmin + (size_t)(b0 + r) * NGRP))[tid];
        const float thr = sthr[r];
        const uint32_t ww[4] = {v.x, v.y, v.z, v.w};
        #pragma unroll
        for (int q = 0; q < 4; ++q) {
            __half2 p = *(const __half2*)&ww[q];
            if (__low2float(p) <= thr) {
                int pp = atomicAdd(&cnt, 1);
                if (pp < 512) grp[pp] = (r << 11) | (tid * 8 + 2 * q);
            }
            if (__high2float(p) <= thr) {
                int pp = atomicAdd(&cnt, 1);
                if (pp < 512) grp[pp] = (r << 11) | (tid * 8 + 2 * q + 1);
            }
        }
    }
    __syncthreads();
    const int ng = min(cnt, 512);
    const int ncand = ng * 8;

    unsigned long long best[4] = {0xFFFFFFFFFFFFFFFFULL, 0xFFFFFFFFFFFFFFFFULL,
                                  0xFFFFFFFFFFFFFFFFULL, 0xFFFFFFFFFFFFFFFFULL};
    for (int ci = wid; ci < ncand; ci += 8) {
        const int code = grp[ci >> 3];
        const int r = code >> 11;
        const int k = (code & 2047) * 8 + (ci & 7);
        const float4* wr = (const float4*)(gWt32 + (size_t)k * DDIM);
        const float4* xr = (const float4*)sx[r];
        float s = 0.f;
        #pragma unroll
        for (int i = 0; i < 4; ++i) {
            float4 w = wr[i * 32 + lane];
            float4 xv = xr[i * 32 + lane];
            s = fmaf(xv.x, w.x, s);
            s = fmaf(xv.y, w.y, s);
            s = fmaf(xv.z, w.z, s);
            s = fmaf(xv.w, w.w, s);
        }
        #pragma unroll
        for (int o = 16; o; o >>= 1) s += __shfl_xor_sync(0xFFFFFFFFu, s, o);
        if (lane == 0) {
            float d2 = g_r[b0 + r] + g_c[k] - 2.f * s;
            unsigned u = __float_as_uint(d2);
            u = (u & 0x80000000u) ? ~u : (u | 0x80000000u);
            unsigned long long key = ((unsigned long long)u << 32) | (unsigned)k;
            if (key < best[r]) best[r] = key;
        }
    }
    if (lane == 0) {
        #pragma unroll
        for (int r = 0; r < 4; ++r) wbest[wid][r] = best[r];
    }
    __syncthreads();

    if (tid < 4) {
        unsigned long long bb = 0xFFFFFFFFFFFFFFFFULL;
        #pragma unroll
        for (int w = 0; w < 8; ++w) if (wbest[w][tid] < bb) bb = wbest[w][tid];
        const int b = b0 + tid;
        unsigned k = (unsigned)(bb & 0xFFFFFFFFu);
        unsigned u = (unsigned)(bb >> 32);
        u = (u & 0x80000000u) ? (u & 0x7FFFFFFFu) : ~u;
        float d2 = __uint_as_float(u);
        g_dist[b] = sqrtf(fmaxf(d2, 0.f));
        out[2 * b] = loc[2 * k];
        if (2 * b + 1 < out_size - 1) out[2 * b + 1] = loc[2 * k + 1];
    }
}

__global__ void loss_kernel(float* __restrict__ out, int out_size) {
    __shared__ float sh[1024];
    float local = 0.f;
    for (int b = threadIdx.x; b < B_ROWS; b += 1024) local += g_dist[b];
    sh[threadIdx.x] = local;
    __syncthreads();
    #pragma unroll
    for (int s = 512; s > 0; s >>= 1) {
        if (threadIdx.x < s) sh[threadIdx.x] += sh[threadIdx.x + s];
        __syncthreads();
    }
    if (threadIdx.x == 0) out[out_size - 1] = sh[0] / (float)B_ROWS;
}

// ---------------------------------------------------------------------------
extern "C" void kernel_launch(void* const* d_in, const int* in_sizes, int n_in,
                              void* d_out, int out_size) {
    const float* X = (const float*)d_in[0];  // (4096, 512)
    const float* W = (const float*)d_in[1];  // (512, 16384)
    const float* L = (const float*)d_in[2];  // (16384, 2)
    float* out = (float*)d_out;

    cudaFuncSetAttribute(gemm_kernel, cudaFuncAttributeMaxDynamicSharedMemorySize, SMEM_TOT);

    prep_kernel<<<8192 + B_ROWS / 2, 256>>>(X, W);
    col_finalize_kernel<<<KN / 256, 256>>>();

    gemm_kernel<<<dim3(KN / 128, B_ROWS / 128), 256, SMEM_TOT>>>();

    refine_kernel<<<B_ROWS / 4, 256>>>(X, L, out, out_size);
    loss_kernel<<<1, 1024>>>(out, out_size);
}